// round 14
// baseline (speedup 1.0000x reference)
#include <cuda_runtime.h>
#include <cstdint>

#define NN 100000
#define EE 600000
#define D  128
#define CAP 64

typedef unsigned long long u64;

// ---------------- scratch (device globals; no allocation allowed) ----------------
__device__ float g_agg[(size_t)NN * D];       // mean-aggregated neighbor features
__device__ float g_h  [(size_t)NN * D];       // layer-1 output (post-ReLU, PRE-BN)
__device__ int   g_adj[(size_t)NN * CAP];     // padded CSR: src ids bucketed by dst
__device__ int   g_bcnt[NN];
__device__ float g_bnsum[D];
__device__ float g_bnsq [D];
__device__ float g_scale[D];
__device__ float g_shift[D];
__device__ float g_bias2[D];                  // b2l + shift @ W2r  (BN fold)

// ---------------- helpers ----------------
__device__ __forceinline__ u64 dup2(float a) {
    u64 r; asm("mov.b64 %0, {%1, %1};" : "=l"(r) : "f"(a)); return r;
}
__device__ __forceinline__ u64 pack2(float lo, float hi) {
    u64 r; asm("mov.b64 %0, {%1, %2};" : "=l"(r) : "f"(lo), "f"(hi)); return r;
}
__device__ __forceinline__ void unpack2(u64 v, float& lo, float& hi) {
    asm("mov.b64 {%0, %1}, %2;" : "=f"(lo), "=f"(hi) : "l"(v));
}
__device__ __forceinline__ void fma2(u64& d, u64 a, u64 b) {
    asm("fma.rn.f32x2 %0, %1, %2, %0;" : "+l"(d) : "l"(a), "l"(b));
}

// ---------------- zero init (bucket counts + BN bins) ----------------
__global__ void zero_kernel() {
    int i = blockIdx.x * blockDim.x + threadIdx.x;
    int stride = gridDim.x * blockDim.x;
    for (int k = i; k < NN; k += stride) g_bcnt[k] = 0;
    if (i < D) { g_bnsum[i] = 0.f; g_bnsq[i] = 0.f; }
}

// ---------------- adjacency build (once, reused both layers) ----------------
__global__ void build_kernel(const int* __restrict__ srcArr,
                             const int* __restrict__ dstArr) {
    int e = blockIdx.x * blockDim.x + threadIdx.x;
    if (e >= EE) return;
    int d = dstArr[e];
    int pos = atomicAdd(&g_bcnt[d], 1);
    if (pos < CAP) g_adj[(size_t)d * CAP + pos] = srcArr[e];
}

// ---------------- gather-mean: one warp per node, unroll-4 for MLP ----------------
__global__ __launch_bounds__(256)
void gather_kernel(const float* __restrict__ xext, int useInternal) {
    int gid  = blockIdx.x * blockDim.x + threadIdx.x;
    int n    = gid >> 5;
    int lane = gid & 31;
    if (n >= NN) return;

    const float* srcF = useInternal ? g_h : xext;

    int cntTrue = g_bcnt[n];
    int cnt = min(cntTrue, CAP);
    const int base = n * CAP;
    const int l4 = lane * 4;

    int a0 = (lane < cnt) ? g_adj[base + lane] : 0;

    float4 acc0 = make_float4(0.f, 0.f, 0.f, 0.f);
    float4 acc1 = make_float4(0.f, 0.f, 0.f, 0.f);
    float4 acc2 = make_float4(0.f, 0.f, 0.f, 0.f);
    float4 acc3 = make_float4(0.f, 0.f, 0.f, 0.f);

    int m = cnt < 32 ? cnt : 32;
    for (int j = 0; j < m; j += 4) {
        int s0 = __shfl_sync(0xffffffffu, a0, j);
        int s1 = __shfl_sync(0xffffffffu, a0, j + 1);
        int s2 = __shfl_sync(0xffffffffu, a0, j + 2);
        int s3 = __shfl_sync(0xffffffffu, a0, j + 3);
        if (j + 0 < m) { float4 v = *reinterpret_cast<const float4*>(srcF + (size_t)s0 * D + l4);
                         acc0.x += v.x; acc0.y += v.y; acc0.z += v.z; acc0.w += v.w; }
        if (j + 1 < m) { float4 v = *reinterpret_cast<const float4*>(srcF + (size_t)s1 * D + l4);
                         acc1.x += v.x; acc1.y += v.y; acc1.z += v.z; acc1.w += v.w; }
        if (j + 2 < m) { float4 v = *reinterpret_cast<const float4*>(srcF + (size_t)s2 * D + l4);
                         acc2.x += v.x; acc2.y += v.y; acc2.z += v.z; acc2.w += v.w; }
        if (j + 3 < m) { float4 v = *reinterpret_cast<const float4*>(srcF + (size_t)s3 * D + l4);
                         acc3.x += v.x; acc3.y += v.y; acc3.z += v.z; acc3.w += v.w; }
    }
    if (cnt > 32) {
        int a1 = (lane + 32 < cnt) ? g_adj[base + 32 + lane] : 0;
        int m2 = cnt - 32;
        for (int j = 0; j < m2; j += 4) {
            int s0 = __shfl_sync(0xffffffffu, a1, j);
            int s1 = __shfl_sync(0xffffffffu, a1, j + 1);
            int s2 = __shfl_sync(0xffffffffu, a1, j + 2);
            int s3 = __shfl_sync(0xffffffffu, a1, j + 3);
            if (j + 0 < m2) { float4 v = *reinterpret_cast<const float4*>(srcF + (size_t)s0 * D + l4);
                              acc0.x += v.x; acc0.y += v.y; acc0.z += v.z; acc0.w += v.w; }
            if (j + 1 < m2) { float4 v = *reinterpret_cast<const float4*>(srcF + (size_t)s1 * D + l4);
                              acc1.x += v.x; acc1.y += v.y; acc1.z += v.z; acc1.w += v.w; }
            if (j + 2 < m2) { float4 v = *reinterpret_cast<const float4*>(srcF + (size_t)s2 * D + l4);
                              acc2.x += v.x; acc2.y += v.y; acc2.z += v.z; acc2.w += v.w; }
            if (j + 3 < m2) { float4 v = *reinterpret_cast<const float4*>(srcF + (size_t)s3 * D + l4);
                              acc3.x += v.x; acc3.y += v.y; acc3.z += v.z; acc3.w += v.w; }
        }
    }

    float4 acc;
    acc.x = (acc0.x + acc1.x) + (acc2.x + acc3.x);
    acc.y = (acc0.y + acc1.y) + (acc2.y + acc3.y);
    acc.z = (acc0.z + acc1.z) + (acc2.z + acc3.z);
    acc.w = (acc0.w + acc1.w) + (acc2.w + acc3.w);

    float rc = 1.0f / fmaxf((float)cntTrue, 1.0f);
    acc.x *= rc; acc.y *= rc; acc.z *= rc; acc.w *= rc;
    if (useInternal && cntTrue > 0) {
        float4 sc = *reinterpret_cast<const float4*>(g_scale + l4);
        float4 sh = *reinterpret_cast<const float4*>(g_shift + l4);
        acc.x = acc.x * sc.x + sh.x;
        acc.y = acc.y * sc.y + sh.y;
        acc.z = acc.z * sc.z + sh.z;
        acc.w = acc.w * sc.w + sh.w;
    }
    *reinterpret_cast<float4*>(g_agg + (size_t)n * D + l4) = acc;
}

// ---------------- node kernel (FFMA2, 16 rows/warp to halve W-LDS per FMA) ----
// block 128 thr (4 warps); warp owns 16 rows; lane owns 4 cols. TM=64, grid same.
// W preloaded per k4 into regs, reused across two 8-row groups.
// Layer2 self pass: BN scale folded into Ws rows; bias from g_bias2.
#define TM 64
#define WPAD 128
#define APAD 128
#define SMEM_FLOATS (128 * WPAD + TM * APAD + D + D)

template <int LAYER>
__global__ __launch_bounds__(128, 2)
void node_kernel(const float* __restrict__ Aself_ext,
                 const float* __restrict__ Wl,
                 const float* __restrict__ Wr,
                 const float* __restrict__ bl,
                 const float* __restrict__ fcW,
                 const float* __restrict__ fcb,
                 float* __restrict__ out) {
    extern __shared__ float smem[];
    float* Ws   = smem;
    float* As   = smem + 128 * WPAD;
    float* sSum = As + TM * APAD;
    float* sSq  = sSum + D;

    const int t  = threadIdx.x;
    const int tx = t & 31;
    const int ty = t >> 5;            // warp 0..3
    const int row0 = blockIdx.x * TM;
    const int c0 = tx << 2;
    const int w16 = ty << 4;          // warp's first row in tile

    const float* Aself = (LAYER == 1) ? Aself_ext : g_h;

    if (t < D) { sSum[t] = 0.f; sSq[t] = 0.f; }

    // acc pairs init with bias (layer2 uses folded bias2)
    u64 acc2[16][2];
    {
        float4 bv;
        if (LAYER == 1) bv = *reinterpret_cast<const float4*>(bl + c0);
        else            bv = *reinterpret_cast<const float4*>(g_bias2 + c0);
        u64 b01 = pack2(bv.x, bv.y);
        u64 b23 = pack2(bv.z, bv.w);
#pragma unroll
        for (int r = 0; r < 16; r++) { acc2[r][0] = b01; acc2[r][1] = b23; }
    }

    for (int pass = 0; pass < 2; ++pass) {
        const float* W = pass ? Wr : Wl;
        __syncthreads();
        // stage W (128x128); layer2 self pass folds BN scale per row
        for (int idx = t; idx < 4096; idx += 128) {
            int k = idx >> 5, j4 = (idx & 31) << 2;
            float4 v = *reinterpret_cast<const float4*>(W + k * D + j4);
            if (LAYER == 2 && pass == 1) {
                float sc = g_scale[k];
                v.x *= sc; v.y *= sc; v.z *= sc; v.w *= sc;
            }
            *reinterpret_cast<float4*>(Ws + k * WPAD + j4) = v;
        }
        // stage A tile (64x128)
        for (int idx = t; idx < 2048; idx += 128) {
            int i = idx >> 5, k4 = (idx & 31) << 2;
            int r = row0 + i;
            float4 v = make_float4(0.f, 0.f, 0.f, 0.f);
            if (r < NN) {
                const float* srcA = pass ? Aself : g_agg;
                v = *reinterpret_cast<const float4*>(srcA + (size_t)r * D + k4);
            }
            *reinterpret_cast<float4*>(As + i * APAD + k4) = v;
        }
        __syncthreads();

#pragma unroll 1
        for (int k4 = 0; k4 < D; k4 += 4) {
            ulonglong2 w[4];
#pragma unroll
            for (int kk = 0; kk < 4; kk++)
                w[kk] = *reinterpret_cast<const ulonglong2*>(Ws + (k4 + kk) * WPAD + c0);
#pragma unroll
            for (int g = 0; g < 2; g++) {
                float4 a[8];
#pragma unroll
                for (int r = 0; r < 8; r++)
                    a[r] = *reinterpret_cast<const float4*>(As + (w16 + g * 8 + r) * APAD + k4);
#pragma unroll
                for (int kk = 0; kk < 4; kk++) {
#pragma unroll
                    for (int r = 0; r < 8; r++) {
                        float av = (kk == 0) ? a[r].x : (kk == 1) ? a[r].y
                                 : (kk == 2) ? a[r].z : a[r].w;
                        u64 ad = dup2(av);
                        fma2(acc2[g * 8 + r][0], ad, w[kk].x);
                        fma2(acc2[g * 8 + r][1], ad, w[kk].y);
                    }
                }
            }
        }
    }

    // ---------------- epilogue ----------------
    float4 fw = make_float4(0.f, 0.f, 0.f, 0.f);
    float fcb0 = 0.f;
    if (LAYER == 2) {
        if (tx < 16) fw = *reinterpret_cast<const float4*>(fcW + c0);
        fcb0 = fcb[0];
    }

    float cs[4] = {0.f, 0.f, 0.f, 0.f};
    float cq[4] = {0.f, 0.f, 0.f, 0.f};

#pragma unroll
    for (int r = 0; r < 16; r++) {
        int row = row0 + w16 + r;
        bool valid = row < NN;
        float a0, a1, a2, a3;
        unpack2(acc2[r][0], a0, a1);
        unpack2(acc2[r][1], a2, a3);

        float ss = a0 * a0 + a1 * a1 + a2 * a2 + a3 * a3;
#pragma unroll
        for (int off = 16; off; off >>= 1)
            ss += __shfl_xor_sync(0xffffffffu, ss, off);
        float inv = 1.0f / fmaxf(sqrtf(ss), 1e-12f);

        float v0 = a0 * inv, v1 = a1 * inv, v2 = a2 * inv, v3 = a3 * inv;

        if (LAYER == 1) {
            v0 = fmaxf(v0, 0.f); v1 = fmaxf(v1, 0.f);
            v2 = fmaxf(v2, 0.f); v3 = fmaxf(v3, 0.f);
            if (valid) {
                *reinterpret_cast<float4*>(g_h + (size_t)row * D + c0) =
                    make_float4(v0, v1, v2, v3);
                cs[0] += v0; cs[1] += v1; cs[2] += v2; cs[3] += v3;
                cq[0] += v0 * v0; cq[1] += v1 * v1;
                cq[2] += v2 * v2; cq[3] += v3 * v3;
            }
        } else {
            if (valid) {
                *reinterpret_cast<float4*>(out + NN + (size_t)row * D + c0) =
                    make_float4(v0, v1, v2, v3);
            }
            float p = 0.f;
            if (tx < 16) p = v0 * fw.x + v1 * fw.y + v2 * fw.z + v3 * fw.w;
#pragma unroll
            for (int off = 16; off; off >>= 1)
                p += __shfl_xor_sync(0xffffffffu, p, off);
            if (tx == 0 && valid) out[row] = p + fcb0;
        }
    }

    if (LAYER == 1) {
#pragma unroll
        for (int c = 0; c < 4; c++) {
            atomicAdd(&sSum[c0 + c], cs[c]);
            atomicAdd(&sSq[c0 + c], cq[c]);
        }
        __syncthreads();
        if (t < D) {
            atomicAdd(&g_bnsum[t], sSum[t]);
            atomicAdd(&g_bnsq[t], sSq[t]);
        }
    }
}

// ---------------- BN finalize ----------------
__global__ void bn_finalize_kernel(const float* __restrict__ gamma,
                                   const float* __restrict__ beta) {
    int t = threadIdx.x;
    float s = g_bnsum[t], q = g_bnsq[t];
    float mu  = s * (1.0f / NN);
    float var = fmaxf(q * (1.0f / NN) - mu * mu, 0.0f);
    float sc  = gamma[t] * rsqrtf(var + 1e-5f);
    g_scale[t] = sc;
    g_shift[t] = beta[t] - mu * sc;
}

// ---------------- fold BN shift through W2r into bias2 ----------------
__global__ void bias2_kernel(const float* __restrict__ W2r,
                             const float* __restrict__ b2l) {
    int c = threadIdx.x;              // 128 threads
    float s = b2l[c];
    for (int k = 0; k < D; k++)
        s += g_shift[k] * W2r[k * D + c];
    g_bias2[c] = s;
}

// ---------------- launch ----------------
extern "C" void kernel_launch(void* const* d_in, const int* in_sizes, int n_in,
                              void* d_out, int out_size) {
    const float* x     = (const float*)d_in[0];
    const int*   ei    = (const int*)  d_in[1];
    const float* W1l   = (const float*)d_in[2];
    const float* b1l   = (const float*)d_in[3];
    const float* W1r   = (const float*)d_in[4];
    const float* gamma = (const float*)d_in[5];
    const float* beta  = (const float*)d_in[6];
    const float* W2l   = (const float*)d_in[7];
    const float* b2l   = (const float*)d_in[8];
    const float* W2r   = (const float*)d_in[9];
    const float* fcW   = (const float*)d_in[10];
    const float* fcb   = (const float*)d_in[11];
    float* out = (float*)d_out;

    const int* src = ei;
    const int* dst = ei + EE;

    const int smemBytes = SMEM_FLOATS * sizeof(float);   // ~97 KB
    cudaFuncSetAttribute(node_kernel<1>, cudaFuncAttributeMaxDynamicSharedMemorySize, smemBytes);
    cudaFuncSetAttribute(node_kernel<2>, cudaFuncAttributeMaxDynamicSharedMemorySize, smemBytes);

    const int nodeBlocks   = (NN + TM - 1) / TM;          // 1563
    const int buildBlocks  = (EE + 255) / 256;            // 2344
    const int gatherBlocks = (NN * 32 + 255) / 256;       // 12500

    zero_kernel<<<512, 256>>>();
    build_kernel<<<buildBlocks, 256>>>(src, dst);
    gather_kernel<<<gatherBlocks, 256>>>(x, 0);
    node_kernel<1><<<nodeBlocks, 128, smemBytes>>>(x, W1l, W1r, b1l, nullptr, nullptr, nullptr);
    bn_finalize_kernel<<<1, 128>>>(gamma, beta);
    bias2_kernel<<<1, 128>>>(W2r, b2l);
    gather_kernel<<<gatherBlocks, 256>>>(nullptr, 1);
    node_kernel<2><<<nodeBlocks, 128, smemBytes>>>(nullptr, W2l, W2r, b2l, fcW, fcb, out);
}

// round 15
// speedup vs baseline: 1.7185x; 1.7185x over previous
#include <cuda_runtime.h>
#include <cstdint>

#define NN 100000
#define EE 600000
#define D  128
#define CAP 64

typedef unsigned long long u64;

// ---------------- scratch (device globals; no allocation allowed) ----------------
__device__ float g_agg[(size_t)NN * D];       // mean-aggregated neighbor features
__device__ float g_h  [(size_t)NN * D];       // layer-1 output (post-ReLU, PRE-BN)
__device__ int   g_adj[(size_t)NN * CAP];     // padded CSR: src ids bucketed by dst
__device__ int   g_bcnt[NN];
__device__ float g_bnsum[D];
__device__ float g_bnsq [D];
__device__ float g_scale[D];
__device__ float g_shift[D];

// ---------------- helpers ----------------
__device__ __forceinline__ u64 dup2(float a) {
    u64 r; asm("mov.b64 %0, {%1, %1};" : "=l"(r) : "f"(a)); return r;
}
__device__ __forceinline__ u64 pack2(float lo, float hi) {
    u64 r; asm("mov.b64 %0, {%1, %2};" : "=l"(r) : "f"(lo), "f"(hi)); return r;
}
__device__ __forceinline__ void unpack2(u64 v, float& lo, float& hi) {
    asm("mov.b64 {%0, %1}, %2;" : "=f"(lo), "=f"(hi) : "l"(v));
}
__device__ __forceinline__ void fma2(u64& d, u64 a, u64 b) {
    asm("fma.rn.f32x2 %0, %1, %2, %0;" : "+l"(d) : "l"(a), "l"(b));
}

// ---------------- zero init (bucket counts + BN bins) ----------------
__global__ void zero_kernel() {
    int i = blockIdx.x * blockDim.x + threadIdx.x;
    int stride = gridDim.x * blockDim.x;
    for (int k = i; k < NN; k += stride) g_bcnt[k] = 0;
    if (i < D) { g_bnsum[i] = 0.f; g_bnsq[i] = 0.f; }
}

// ---------------- adjacency build (once, reused both layers) ----------------
__global__ void build_kernel(const int* __restrict__ srcArr,
                             const int* __restrict__ dstArr) {
    int e = blockIdx.x * blockDim.x + threadIdx.x;
    if (e >= EE) return;
    int d = dstArr[e];
    int pos = atomicAdd(&g_bcnt[d], 1);
    if (pos < CAP) g_adj[(size_t)d * CAP + pos] = srcArr[e];
}

// ---------------- gather-mean: one warp per node, uniform int4 id loads ----------
// Neighbor ids fetched 4-at-a-time via warp-uniform LDG.128 (base is 16B-aligned,
// CAP=64) — no shfl chain, no lane-conditional preload. 4 independent
// accumulators keep MLP=4 on the row loads.
__global__ __launch_bounds__(256)
void gather_kernel(const float* __restrict__ xext, int useInternal) {
    int gid  = blockIdx.x * blockDim.x + threadIdx.x;
    int n    = gid >> 5;
    int lane = gid & 31;
    if (n >= NN) return;

    const float* srcF = useInternal ? g_h : xext;

    int cntTrue = g_bcnt[n];
    int cnt = min(cntTrue, CAP);
    const int base = n * CAP;
    const int l4 = lane * 4;

    float4 acc0 = make_float4(0.f, 0.f, 0.f, 0.f);
    float4 acc1 = make_float4(0.f, 0.f, 0.f, 0.f);
    float4 acc2 = make_float4(0.f, 0.f, 0.f, 0.f);
    float4 acc3 = make_float4(0.f, 0.f, 0.f, 0.f);

    for (int j = 0; j < cnt; j += 4) {
        int4 ids = *reinterpret_cast<const int4*>(g_adj + base + j);
        if (j + 0 < cnt) { float4 v = *reinterpret_cast<const float4*>(srcF + (size_t)ids.x * D + l4);
                           acc0.x += v.x; acc0.y += v.y; acc0.z += v.z; acc0.w += v.w; }
        if (j + 1 < cnt) { float4 v = *reinterpret_cast<const float4*>(srcF + (size_t)ids.y * D + l4);
                           acc1.x += v.x; acc1.y += v.y; acc1.z += v.z; acc1.w += v.w; }
        if (j + 2 < cnt) { float4 v = *reinterpret_cast<const float4*>(srcF + (size_t)ids.z * D + l4);
                           acc2.x += v.x; acc2.y += v.y; acc2.z += v.z; acc2.w += v.w; }
        if (j + 3 < cnt) { float4 v = *reinterpret_cast<const float4*>(srcF + (size_t)ids.w * D + l4);
                           acc3.x += v.x; acc3.y += v.y; acc3.z += v.z; acc3.w += v.w; }
    }

    float4 acc;
    acc.x = (acc0.x + acc1.x) + (acc2.x + acc3.x);
    acc.y = (acc0.y + acc1.y) + (acc2.y + acc3.y);
    acc.z = (acc0.z + acc1.z) + (acc2.z + acc3.z);
    acc.w = (acc0.w + acc1.w) + (acc2.w + acc3.w);

    float rc = 1.0f / fmaxf((float)cntTrue, 1.0f);
    acc.x *= rc; acc.y *= rc; acc.z *= rc; acc.w *= rc;
    if (useInternal && cntTrue > 0) {
        float4 sc = *reinterpret_cast<const float4*>(g_scale + l4);
        float4 sh = *reinterpret_cast<const float4*>(g_shift + l4);
        acc.x = acc.x * sc.x + sh.x;
        acc.y = acc.y * sc.y + sh.y;
        acc.z = acc.z * sc.z + sh.z;
        acc.w = acc.w * sc.w + sh.w;
    }
    *reinterpret_cast<float4*>(g_agg + (size_t)n * D + l4) = acc;
}

// ---------------- node kernel (FFMA2) — FROZEN at measured-best R10 shape ----------
// block: 256 threads. tile: 64 rows x 128 cols. micro-tile: 8 rows x 4 cols.
#define TM 64
#define WPAD 132
#define SMEM_FLOATS (128 * WPAD + TM * WPAD + D + D)

template <int LAYER>
__global__ __launch_bounds__(256, 2)
void node_kernel(const float* __restrict__ Aself_ext,
                 const float* __restrict__ Wl,
                 const float* __restrict__ Wr,
                 const float* __restrict__ bl,
                 const float* __restrict__ fcW,
                 const float* __restrict__ fcb,
                 float* __restrict__ out) {
    extern __shared__ float smem[];
    float* Ws   = smem;
    float* As   = smem + 128 * WPAD;
    float* sSum = As + TM * WPAD;
    float* sSq  = sSum + D;

    const int t  = threadIdx.x;
    const int tx = t & 31;
    const int ty = t >> 5;
    const int row0 = blockIdx.x * TM;
    const int c0 = tx << 2;
    const int ty8 = ty << 3;

    const float* Aself = (LAYER == 1) ? Aself_ext : g_h;

    if (t < D) { sSum[t] = 0.f; sSq[t] = 0.f; }

    // acc pairs init with bias (added once)
    float4 bv = *reinterpret_cast<const float4*>(bl + c0);
    u64 acc2[8][2];
    {
        u64 b01 = pack2(bv.x, bv.y);
        u64 b23 = pack2(bv.z, bv.w);
#pragma unroll
        for (int r = 0; r < 8; r++) { acc2[r][0] = b01; acc2[r][1] = b23; }
    }

    for (int pass = 0; pass < 2; ++pass) {
        const float* W = pass ? Wr : Wl;
        __syncthreads();
        // stage W (128x128) into padded smem
        for (int idx = t; idx < 4096; idx += 256) {
            int k = idx >> 5, j4 = (idx & 31) << 2;
            *reinterpret_cast<float4*>(Ws + k * WPAD + j4) =
                *reinterpret_cast<const float4*>(W + k * D + j4);
        }
        // stage A tile (64x128); layer-2 self pass applies BN affine here
        for (int idx = t; idx < 2048; idx += 256) {
            int i = idx >> 5, k4 = (idx & 31) << 2;
            int r = row0 + i;
            float4 v = make_float4(0.f, 0.f, 0.f, 0.f);
            if (r < NN) {
                const float* srcA = pass ? Aself : g_agg;
                v = *reinterpret_cast<const float4*>(srcA + (size_t)r * D + k4);
                if (LAYER == 2 && pass == 1) {
                    float4 sc = *reinterpret_cast<const float4*>(g_scale + k4);
                    float4 sh = *reinterpret_cast<const float4*>(g_shift + k4);
                    v.x = v.x * sc.x + sh.x; v.y = v.y * sc.y + sh.y;
                    v.z = v.z * sc.z + sh.z; v.w = v.w * sc.w + sh.w;
                }
            }
            *reinterpret_cast<float4*>(As + i * WPAD + k4) = v;
        }
        __syncthreads();

#pragma unroll 2
        for (int k4 = 0; k4 < D; k4 += 4) {
            float4 a[8];
#pragma unroll
            for (int r = 0; r < 8; r++)
                a[r] = *reinterpret_cast<const float4*>(As + (ty8 + r) * WPAD + k4);
#pragma unroll
            for (int kk = 0; kk < 4; kk++) {
                ulonglong2 w = *reinterpret_cast<const ulonglong2*>(Ws + (k4 + kk) * WPAD + c0);
#pragma unroll
                for (int r = 0; r < 8; r++) {
                    float av = (kk == 0) ? a[r].x : (kk == 1) ? a[r].y
                             : (kk == 2) ? a[r].z : a[r].w;
                    u64 ad = dup2(av);
                    fma2(acc2[r][0], ad, w.x);
                    fma2(acc2[r][1], ad, w.y);
                }
            }
        }
    }

    // ---------------- epilogue ----------------
    float4 fw = make_float4(0.f, 0.f, 0.f, 0.f);
    float fcb0 = 0.f;
    if (LAYER == 2) {
        if (tx < 16) fw = *reinterpret_cast<const float4*>(fcW + c0);
        fcb0 = fcb[0];
    }

    float cs[4] = {0.f, 0.f, 0.f, 0.f};
    float cq[4] = {0.f, 0.f, 0.f, 0.f};

#pragma unroll
    for (int r = 0; r < 8; r++) {
        int row = row0 + ty8 + r;
        bool valid = row < NN;
        float a0, a1, a2, a3;
        unpack2(acc2[r][0], a0, a1);
        unpack2(acc2[r][1], a2, a3);

        float ss = a0 * a0 + a1 * a1 + a2 * a2 + a3 * a3;
#pragma unroll
        for (int off = 16; off; off >>= 1)
            ss += __shfl_xor_sync(0xffffffffu, ss, off);
        float inv = 1.0f / fmaxf(sqrtf(ss), 1e-12f);

        float v0 = a0 * inv, v1 = a1 * inv, v2 = a2 * inv, v3 = a3 * inv;

        if (LAYER == 1) {
            v0 = fmaxf(v0, 0.f); v1 = fmaxf(v1, 0.f);
            v2 = fmaxf(v2, 0.f); v3 = fmaxf(v3, 0.f);
            if (valid) {
                *reinterpret_cast<float4*>(g_h + (size_t)row * D + c0) =
                    make_float4(v0, v1, v2, v3);
                cs[0] += v0; cs[1] += v1; cs[2] += v2; cs[3] += v3;
                cq[0] += v0 * v0; cq[1] += v1 * v1;
                cq[2] += v2 * v2; cq[3] += v3 * v3;
            }
        } else {
            if (valid) {
                *reinterpret_cast<float4*>(out + NN + (size_t)row * D + c0) =
                    make_float4(v0, v1, v2, v3);
            }
            float p = 0.f;
            if (tx < 16) p = v0 * fw.x + v1 * fw.y + v2 * fw.z + v3 * fw.w;
#pragma unroll
            for (int off = 16; off; off >>= 1)
                p += __shfl_xor_sync(0xffffffffu, p, off);
            if (tx == 0 && valid) out[row] = p + fcb0;
        }
    }

    if (LAYER == 1) {
#pragma unroll
        for (int c = 0; c < 4; c++) {
            atomicAdd(&sSum[c0 + c], cs[c]);
            atomicAdd(&sSq[c0 + c], cq[c]);
        }
        __syncthreads();
        if (t < D) {
            atomicAdd(&g_bnsum[t], sSum[t]);
            atomicAdd(&g_bnsq[t], sSq[t]);
        }
    }
}

// ---------------- BN finalize ----------------
__global__ void bn_finalize_kernel(const float* __restrict__ gamma,
                                   const float* __restrict__ beta) {
    int t = threadIdx.x;
    float s = g_bnsum[t], q = g_bnsq[t];
    float mu  = s * (1.0f / NN);
    float var = fmaxf(q * (1.0f / NN) - mu * mu, 0.0f);
    float sc  = gamma[t] * rsqrtf(var + 1e-5f);
    g_scale[t] = sc;
    g_shift[t] = beta[t] - mu * sc;
}

// ---------------- launch ----------------
extern "C" void kernel_launch(void* const* d_in, const int* in_sizes, int n_in,
                              void* d_out, int out_size) {
    const float* x     = (const float*)d_in[0];
    const int*   ei    = (const int*)  d_in[1];
    const float* W1l   = (const float*)d_in[2];
    const float* b1l   = (const float*)d_in[3];
    const float* W1r   = (const float*)d_in[4];
    const float* gamma = (const float*)d_in[5];
    const float* beta  = (const float*)d_in[6];
    const float* W2l   = (const float*)d_in[7];
    const float* b2l   = (const float*)d_in[8];
    const float* W2r   = (const float*)d_in[9];
    const float* fcW   = (const float*)d_in[10];
    const float* fcb   = (const float*)d_in[11];
    float* out = (float*)d_out;

    const int* src = ei;
    const int* dst = ei + EE;

    const int smemBytes = SMEM_FLOATS * sizeof(float);
    cudaFuncSetAttribute(node_kernel<1>, cudaFuncAttributeMaxDynamicSharedMemorySize, smemBytes);
    cudaFuncSetAttribute(node_kernel<2>, cudaFuncAttributeMaxDynamicSharedMemorySize, smemBytes);

    const int nodeBlocks   = (NN + TM - 1) / TM;          // 1563
    const int buildBlocks  = (EE + 255) / 256;            // 2344
    const int gatherBlocks = (NN * 32 + 255) / 256;       // 12500

    zero_kernel<<<512, 256>>>();
    build_kernel<<<buildBlocks, 256>>>(src, dst);
    gather_kernel<<<gatherBlocks, 256>>>(x, 0);
    node_kernel<1><<<nodeBlocks, 256, smemBytes>>>(x, W1l, W1r, b1l, nullptr, nullptr, nullptr);
    bn_finalize_kernel<<<1, 128>>>(gamma, beta);
    gather_kernel<<<gatherBlocks, 256>>>(nullptr, 1);
    node_kernel<2><<<nodeBlocks, 256, smemBytes>>>(nullptr, W2l, W2r, b2l, fcW, fcb, out);
}

// round 17
// speedup vs baseline: 1.7631x; 1.0260x over previous
#include <cuda_runtime.h>
#include <cstdint>

#define NN 100000
#define EE 600000
#define D  128
#define CAP 64

typedef unsigned long long u64;

// ---------------- scratch (device globals; no allocation allowed) ----------------
__device__ float g_agg[(size_t)NN * D];       // mean-aggregated neighbor features
__device__ float g_h  [(size_t)NN * D];       // layer-1 output (post-ReLU, PRE-BN)
__device__ int   g_adj[(size_t)NN * CAP];     // padded CSR: src ids bucketed by dst
__device__ int   g_bcnt[NN];
__device__ float g_bnsum[D];
__device__ float g_bnsq [D];
__device__ float g_scale[D];
__device__ float g_shift[D];

// ---------------- helpers ----------------
__device__ __forceinline__ u64 dup2(float a) {
    u64 r; asm("mov.b64 %0, {%1, %1};" : "=l"(r) : "f"(a)); return r;
}
__device__ __forceinline__ u64 pack2(float lo, float hi) {
    u64 r; asm("mov.b64 %0, {%1, %2};" : "=l"(r) : "f"(lo), "f"(hi)); return r;
}
__device__ __forceinline__ void unpack2(u64 v, float& lo, float& hi) {
    asm("mov.b64 {%0, %1}, %2;" : "=f"(lo), "=f"(hi) : "l"(v));
}
__device__ __forceinline__ void fma2(u64& d, u64 a, u64 b) {
    asm("fma.rn.f32x2 %0, %1, %2, %0;" : "+l"(d) : "l"(a), "l"(b));
}

// ---------------- zero init (bucket counts + BN bins) ----------------
__global__ void zero_kernel() {
    int i = blockIdx.x * blockDim.x + threadIdx.x;
    int stride = gridDim.x * blockDim.x;
    for (int k = i; k < NN; k += stride) g_bcnt[k] = 0;
    if (i < D) { g_bnsum[i] = 0.f; g_bnsq[i] = 0.f; }
}

// ---------------- adjacency build (once, reused both layers) ----------------
__global__ void build_kernel(const int* __restrict__ srcArr,
                             const int* __restrict__ dstArr) {
    int e = blockIdx.x * blockDim.x + threadIdx.x;
    if (e >= EE) return;
    int d = dstArr[e];
    int pos = atomicAdd(&g_bcnt[d], 1);
    if (pos < CAP) g_adj[(size_t)d * CAP + pos] = srcArr[e];
}

// ---------------- gather-mean: TWO nodes per warp (MLP 8), no atomics ----------
// Uniform int4 id loads per node; all row loads predicated; separate
// accumulators per node. BN affine applied post-mean for layer-2 (cnt>0 only).
__global__ __launch_bounds__(256)
void gather_kernel(const float* __restrict__ xext, int useInternal) {
    int gid  = blockIdx.x * blockDim.x + threadIdx.x;
    int w    = gid >> 5;
    int lane = gid & 31;
    int n0   = w * 2;
    if (n0 >= NN) return;
    int n1 = n0 + 1;
    bool has1 = n1 < NN;

    const float* srcF = useInternal ? g_h : xext;
    const int l4 = lane * 4;

    int c0t = g_bcnt[n0];
    int c1t = has1 ? g_bcnt[n1] : 0;
    int cnt0 = min(c0t, CAP);
    int cnt1 = min(c1t, CAP);
    int mx = max(cnt0, cnt1);
    const int b0 = n0 * CAP;
    const int b1 = n1 * CAP;

    float4 p0 = make_float4(0.f, 0.f, 0.f, 0.f);
    float4 q0 = make_float4(0.f, 0.f, 0.f, 0.f);
    float4 p1 = make_float4(0.f, 0.f, 0.f, 0.f);
    float4 q1 = make_float4(0.f, 0.f, 0.f, 0.f);

    for (int j = 0; j < mx; j += 4) {
        int4 i0 = *reinterpret_cast<const int4*>(g_adj + b0 + j);
        int4 i1 = has1 ? *reinterpret_cast<const int4*>(g_adj + b1 + j)
                       : make_int4(0, 0, 0, 0);
        if (j + 0 < cnt0) { float4 v = *reinterpret_cast<const float4*>(srcF + (size_t)i0.x * D + l4);
                            p0.x += v.x; p0.y += v.y; p0.z += v.z; p0.w += v.w; }
        if (j + 0 < cnt1) { float4 v = *reinterpret_cast<const float4*>(srcF + (size_t)i1.x * D + l4);
                            p1.x += v.x; p1.y += v.y; p1.z += v.z; p1.w += v.w; }
        if (j + 1 < cnt0) { float4 v = *reinterpret_cast<const float4*>(srcF + (size_t)i0.y * D + l4);
                            q0.x += v.x; q0.y += v.y; q0.z += v.z; q0.w += v.w; }
        if (j + 1 < cnt1) { float4 v = *reinterpret_cast<const float4*>(srcF + (size_t)i1.y * D + l4);
                            q1.x += v.x; q1.y += v.y; q1.z += v.z; q1.w += v.w; }
        if (j + 2 < cnt0) { float4 v = *reinterpret_cast<const float4*>(srcF + (size_t)i0.z * D + l4);
                            p0.x += v.x; p0.y += v.y; p0.z += v.z; p0.w += v.w; }
        if (j + 2 < cnt1) { float4 v = *reinterpret_cast<const float4*>(srcF + (size_t)i1.z * D + l4);
                            p1.x += v.x; p1.y += v.y; p1.z += v.z; p1.w += v.w; }
        if (j + 3 < cnt0) { float4 v = *reinterpret_cast<const float4*>(srcF + (size_t)i0.w * D + l4);
                            q0.x += v.x; q0.y += v.y; q0.z += v.z; q0.w += v.w; }
        if (j + 3 < cnt1) { float4 v = *reinterpret_cast<const float4*>(srcF + (size_t)i1.w * D + l4);
                            q1.x += v.x; q1.y += v.y; q1.z += v.z; q1.w += v.w; }
    }

    float4 sc = make_float4(1.f, 1.f, 1.f, 1.f);
    float4 sh = make_float4(0.f, 0.f, 0.f, 0.f);
    if (useInternal) {
        sc = *reinterpret_cast<const float4*>(g_scale + l4);
        sh = *reinterpret_cast<const float4*>(g_shift + l4);
    }

    {
        float rc = 1.0f / fmaxf((float)c0t, 1.0f);
        float4 a;
        a.x = (p0.x + q0.x) * rc; a.y = (p0.y + q0.y) * rc;
        a.z = (p0.z + q0.z) * rc; a.w = (p0.w + q0.w) * rc;
        if (useInternal && c0t > 0) {
            a.x = a.x * sc.x + sh.x; a.y = a.y * sc.y + sh.y;
            a.z = a.z * sc.z + sh.z; a.w = a.w * sc.w + sh.w;
        }
        *reinterpret_cast<float4*>(g_agg + (size_t)n0 * D + l4) = a;
    }
    if (has1) {
        float rc = 1.0f / fmaxf((float)c1t, 1.0f);
        float4 a;
        a.x = (p1.x + q1.x) * rc; a.y = (p1.y + q1.y) * rc;
        a.z = (p1.z + q1.z) * rc; a.w = (p1.w + q1.w) * rc;
        if (useInternal && c1t > 0) {
            a.x = a.x * sc.x + sh.x; a.y = a.y * sc.y + sh.y;
            a.z = a.z * sc.z + sh.z; a.w = a.w * sc.w + sh.w;
        }
        *reinterpret_cast<float4*>(g_agg + (size_t)n1 * D + l4) = a;
    }
}

// ---------------- node kernel (FFMA2) — FROZEN at measured-best R10 shape ----------
// block: 256 threads. tile: 64 rows x 128 cols. micro-tile: 8 rows x 4 cols.
#define TM 64
#define WPAD 132
#define SMEM_FLOATS (128 * WPAD + TM * WPAD + D + D)

template <int LAYER>
__global__ __launch_bounds__(256, 2)
void node_kernel(const float* __restrict__ Aself_ext,
                 const float* __restrict__ Wl,
                 const float* __restrict__ Wr,
                 const float* __restrict__ bl,
                 const float* __restrict__ fcW,
                 const float* __restrict__ fcb,
                 float* __restrict__ out) {
    extern __shared__ float smem[];
    float* Ws   = smem;
    float* As   = smem + 128 * WPAD;
    float* sSum = As + TM * WPAD;
    float* sSq  = sSum + D;

    const int t  = threadIdx.x;
    const int tx = t & 31;
    const int ty = t >> 5;
    const int row0 = blockIdx.x * TM;
    const int c0 = tx << 2;
    const int ty8 = ty << 3;

    const float* Aself = (LAYER == 1) ? Aself_ext : g_h;

    if (t < D) { sSum[t] = 0.f; sSq[t] = 0.f; }

    // acc pairs init with bias (added once)
    float4 bv = *reinterpret_cast<const float4*>(bl + c0);
    u64 acc2[8][2];
    {
        u64 b01 = pack2(bv.x, bv.y);
        u64 b23 = pack2(bv.z, bv.w);
#pragma unroll
        for (int r = 0; r < 8; r++) { acc2[r][0] = b01; acc2[r][1] = b23; }
    }

    for (int pass = 0; pass < 2; ++pass) {
        const float* W = pass ? Wr : Wl;
        __syncthreads();
        // stage W (128x128) into padded smem
        for (int idx = t; idx < 4096; idx += 256) {
            int k = idx >> 5, j4 = (idx & 31) << 2;
            *reinterpret_cast<float4*>(Ws + k * WPAD + j4) =
                *reinterpret_cast<const float4*>(W + k * D + j4);
        }
        // stage A tile (64x128); layer-2 self pass applies BN affine here
        for (int idx = t; idx < 2048; idx += 256) {
            int i = idx >> 5, k4 = (idx & 31) << 2;
            int r = row0 + i;
            float4 v = make_float4(0.f, 0.f, 0.f, 0.f);
            if (r < NN) {
                const float* srcA = pass ? Aself : g_agg;
                v = *reinterpret_cast<const float4*>(srcA + (size_t)r * D + k4);
                if (LAYER == 2 && pass == 1) {
                    float4 sc = *reinterpret_cast<const float4*>(g_scale + k4);
                    float4 sh = *reinterpret_cast<const float4*>(g_shift + k4);
                    v.x = v.x * sc.x + sh.x; v.y = v.y * sc.y + sh.y;
                    v.z = v.z * sc.z + sh.z; v.w = v.w * sc.w + sh.w;
                }
            }
            *reinterpret_cast<float4*>(As + i * WPAD + k4) = v;
        }
        __syncthreads();

#pragma unroll 2
        for (int k4 = 0; k4 < D; k4 += 4) {
            float4 a[8];
#pragma unroll
            for (int r = 0; r < 8; r++)
                a[r] = *reinterpret_cast<const float4*>(As + (ty8 + r) * WPAD + k4);
#pragma unroll
            for (int kk = 0; kk < 4; kk++) {
                ulonglong2 w = *reinterpret_cast<const ulonglong2*>(Ws + (k4 + kk) * WPAD + c0);
#pragma unroll
                for (int r = 0; r < 8; r++) {
                    float av = (kk == 0) ? a[r].x : (kk == 1) ? a[r].y
                             : (kk == 2) ? a[r].z : a[r].w;
                    u64 ad = dup2(av);
                    fma2(acc2[r][0], ad, w.x);
                    fma2(acc2[r][1], ad, w.y);
                }
            }
        }
    }

    // ---------------- epilogue ----------------
    float4 fw = make_float4(0.f, 0.f, 0.f, 0.f);
    float fcb0 = 0.f;
    if (LAYER == 2) {
        if (tx < 16) fw = *reinterpret_cast<const float4*>(fcW + c0);
        fcb0 = fcb[0];
    }

    float cs[4] = {0.f, 0.f, 0.f, 0.f};
    float cq[4] = {0.f, 0.f, 0.f, 0.f};

#pragma unroll
    for (int r = 0; r < 8; r++) {
        int row = row0 + ty8 + r;
        bool valid = row < NN;
        float a0, a1, a2, a3;
        unpack2(acc2[r][0], a0, a1);
        unpack2(acc2[r][1], a2, a3);

        float ss = a0 * a0 + a1 * a1 + a2 * a2 + a3 * a3;
#pragma unroll
        for (int off = 16; off; off >>= 1)
            ss += __shfl_xor_sync(0xffffffffu, ss, off);
        float inv = 1.0f / fmaxf(sqrtf(ss), 1e-12f);

        float v0 = a0 * inv, v1 = a1 * inv, v2 = a2 * inv, v3 = a3 * inv;

        if (LAYER == 1) {
            v0 = fmaxf(v0, 0.f); v1 = fmaxf(v1, 0.f);
            v2 = fmaxf(v2, 0.f); v3 = fmaxf(v3, 0.f);
            if (valid) {
                *reinterpret_cast<float4*>(g_h + (size_t)row * D + c0) =
                    make_float4(v0, v1, v2, v3);
                cs[0] += v0; cs[1] += v1; cs[2] += v2; cs[3] += v3;
                cq[0] += v0 * v0; cq[1] += v1 * v1;
                cq[2] += v2 * v2; cq[3] += v3 * v3;
            }
        } else {
            if (valid) {
                *reinterpret_cast<float4*>(out + NN + (size_t)row * D + c0) =
                    make_float4(v0, v1, v2, v3);
            }
            float p = 0.f;
            if (tx < 16) p = v0 * fw.x + v1 * fw.y + v2 * fw.z + v3 * fw.w;
#pragma unroll
            for (int off = 16; off; off >>= 1)
                p += __shfl_xor_sync(0xffffffffu, p, off);
            if (tx == 0 && valid) out[row] = p + fcb0;
        }
    }

    if (LAYER == 1) {
#pragma unroll
        for (int c = 0; c < 4; c++) {
            atomicAdd(&sSum[c0 + c], cs[c]);
            atomicAdd(&sSq[c0 + c], cq[c]);
        }
        __syncthreads();
        if (t < D) {
            atomicAdd(&g_bnsum[t], sSum[t]);
            atomicAdd(&g_bnsq[t], sSq[t]);
        }
    }
}

// ---------------- BN finalize ----------------
__global__ void bn_finalize_kernel(const float* __restrict__ gamma,
                                   const float* __restrict__ beta) {
    int t = threadIdx.x;
    float s = g_bnsum[t], q = g_bnsq[t];
    float mu  = s * (1.0f / NN);
    float var = fmaxf(q * (1.0f / NN) - mu * mu, 0.0f);
    float sc  = gamma[t] * rsqrtf(var + 1e-5f);
    g_scale[t] = sc;
    g_shift[t] = beta[t] - mu * sc;
}

// ---------------- launch ----------------
extern "C" void kernel_launch(void* const* d_in, const int* in_sizes, int n_in,
                              void* d_out, int out_size) {
    const float* x     = (const float*)d_in[0];
    const int*   ei    = (const int*)  d_in[1];
    const float* W1l   = (const float*)d_in[2];
    const float* b1l   = (const float*)d_in[3];
    const float* W1r   = (const float*)d_in[4];
    const float* gamma = (const float*)d_in[5];
    const float* beta  = (const float*)d_in[6];
    const float* W2l   = (const float*)d_in[7];
    const float* b2l   = (const float*)d_in[8];
    const float* W2r   = (const float*)d_in[9];
    const float* fcW   = (const float*)d_in[10];
    const float* fcb   = (const float*)d_in[11];
    float* out = (float*)d_out;

    const int* src = ei;
    const int* dst = ei + EE;

    const int smemBytes = SMEM_FLOATS * sizeof(float);
    cudaFuncSetAttribute(node_kernel<1>, cudaFuncAttributeMaxDynamicSharedMemorySize, smemBytes);
    cudaFuncSetAttribute(node_kernel<2>, cudaFuncAttributeMaxDynamicSharedMemorySize, smemBytes);

    const int nodeBlocks   = (NN + TM - 1) / TM;              // 1563
    const int buildBlocks  = (EE + 255) / 256;                // 2344
    const int gatherBlocks = ((NN + 1) / 2 * 32 + 255) / 256; // 6250

    zero_kernel<<<512, 256>>>();
    build_kernel<<<buildBlocks, 256>>>(src, dst);
    gather_kernel<<<gatherBlocks, 256>>>(x, 0);
    node_kernel<1><<<nodeBlocks, 256, smemBytes>>>(x, W1l, W1r, b1l, nullptr, nullptr, nullptr);
    bn_finalize_kernel<<<1, 128>>>(gamma, beta);
    gather_kernel<<<gatherBlocks, 256>>>(nullptr, 1);
    node_kernel<2><<<nodeBlocks, 256, smemBytes>>>(nullptr, W2l, W2r, b2l, fcW, fcb, out);
}